// round 1
// baseline (speedup 1.0000x reference)
#include <cuda_runtime.h>
#include <cuda_bf16.h>
#include <math.h>

// Problem dims (fixed for this problem instance)
#define BB 8
#define NN 100
#define DD 768
#define HH 768
#define TT 577
#define TH 24
#define BN (BB*NN)        // 800

// Scratch (device globals; no allocation allowed)
__device__ float g_pooled[BN * DD];
__device__ float g_ha[BN * HH];
__device__ float g_hb[BN * HH];

// ---------------------------------------------------------------------------
// Kernel 1: ROI mean pool.  grid = 800 blocks (one per (b,n)), 256 threads.
// ---------------------------------------------------------------------------
__global__ void pool_kernel(const float* __restrict__ pt,
                            const float* __restrict__ boxes,
                            const int* __restrict__ imh,
                            const int* __restrict__ imw) {
    int bn = blockIdx.x;
    int b = bn / NN;
    const float* box = boxes + bn * 4;

    float sizeW = (float)(*imw);
    float sizeH = (float)(*imh);

    // Replicate reference coordinate chain exactly in IEEE fp32:
    // pix = floor(v*size); p = floor(pix/size*th)
    float v0 = box[0], v1 = box[1], v2 = box[2], v3 = box[3];
    int px1 = (int)floorf(floorf(v0 * sizeW) / sizeW * (float)TH);
    int py1 = (int)floorf(floorf(v1 * sizeH) / sizeH * (float)TH);
    int px2 = (int)floorf(floorf(v2 * sizeW) / sizeW * (float)TH);
    int py2 = (int)floorf(floorf(v3 * sizeH) / sizeH * (float)TH);
    px1 = min(max(px1, 0), TH - 1);
    py1 = min(max(py1, 0), TH - 1);
    px2 = min(max(px2, 1), TH);
    py2 = min(max(py2, 1), TH);
    if (px2 <= px1) px2 = px1 + 1;
    if (py2 <= py1) py2 = py1 + 1;

    float cnt = (float)((px2 - px1) * (py2 - py1));

    const float* base = pt + ((size_t)b * TT + 1) * DD;  // skip CLS token
    for (int d = threadIdx.x; d < DD; d += 256) {
        float s = 0.f;
        for (int y = py1; y < py2; y++) {
            const float* rowp = base + (size_t)(y * TH) * DD + d;
            for (int x = px1; x < px2; x++) {
                s += rowp[(size_t)x * DD];
            }
        }
        g_pooled[(size_t)bn * DD + d] = s / cnt;
    }
}

// ---------------------------------------------------------------------------
// Kernel 2: GEMM  C[s] = pooled[800,768] @ W1[s*768:(s+1)*768, 768]
// 64x64x16 tiles, 256 threads, 4x4 microtile. grid = (12, 13, 2)
// ---------------------------------------------------------------------------
__global__ void gemm_kernel(const float* __restrict__ W1) {
    const int BM = 64, BNt = 64, BK = 16;
    int s = blockIdx.z;
    const float* Bmat = W1 + (size_t)s * DD * HH;   // [768,768] row-major
    float* C = s ? g_hb : g_ha;

    int m0 = blockIdx.y * BM;
    int n0 = blockIdx.x * BNt;

    __shared__ float As[BK][BM + 4];   // k-major, padded (float4-aligned pitch)
    __shared__ float Bs[BK][BNt + 4];

    int tid = threadIdx.x;
    int tx = tid % 16, ty = tid / 16;

    float acc[4][4] = {};

    for (int k0 = 0; k0 < DD; k0 += BK) {
        // Load A tile 64x16 (transposed into As[k][m])
        #pragma unroll
        for (int t = 0; t < 4; t++) {
            int idx = tid + t * 256;
            int r = idx / BK, c = idx % BK;
            int m = m0 + r;
            float v = 0.f;
            if (m < BN) v = g_pooled[(size_t)m * DD + k0 + c];
            As[c][r] = v;
        }
        // Load B tile 16x64
        #pragma unroll
        for (int t = 0; t < 4; t++) {
            int idx = tid + t * 256;
            int r = idx / BNt, c = idx % BNt;
            Bs[r][c] = Bmat[(size_t)(k0 + r) * HH + n0 + c];
        }
        __syncthreads();

        #pragma unroll
        for (int kk = 0; kk < BK; kk++) {
            float4 a4 = *(const float4*)&As[kk][ty * 4];
            float4 b4 = *(const float4*)&Bs[kk][tx * 4];
            float a[4] = {a4.x, a4.y, a4.z, a4.w};
            float bv[4] = {b4.x, b4.y, b4.z, b4.w};
            #pragma unroll
            for (int i = 0; i < 4; i++)
                #pragma unroll
                for (int j = 0; j < 4; j++)
                    acc[i][j] += a[i] * bv[j];
        }
        __syncthreads();
    }

    #pragma unroll
    for (int i = 0; i < 4; i++) {
        int m = m0 + ty * 4 + i;
        if (m < BN) {
            #pragma unroll
            for (int j = 0; j < 4; j++)
                C[(size_t)m * HH + n0 + tx * 4 + j] = acc[i][j];
        }
    }
}

// ---------------------------------------------------------------------------
// Kernel 3: pairwise relu-dot + sigmoid.
// out[b,i,j] = sigmoid( sum_h relu(ha[b,i,h]+hb[b,j,h]+b1[h]) * W2[h] + b2 )
// 32x32 (i,j) tile per block, 256 threads, 2x2 per thread. grid = (4,4,8)
// ---------------------------------------------------------------------------
__global__ void pair_kernel(const float* __restrict__ b1,
                            const float* __restrict__ W2,
                            const float* __restrict__ b2,
                            float* __restrict__ out) {
    int b = blockIdx.z;
    int i0 = blockIdx.y * 32;
    int j0 = blockIdx.x * 32;

    __shared__ float has[32][33];   // k-major: has[kk][row]
    __shared__ float hbs[32][33];
    __shared__ float b1s[32];
    __shared__ float w2s[32];

    int tid = threadIdx.x;
    int tx = tid % 16, ty = tid / 16;

    float acc[2][2] = {};

    for (int k0 = 0; k0 < HH; k0 += 32) {
        #pragma unroll
        for (int t = 0; t < 4; t++) {
            int idx = tid + t * 256;
            int r = idx / 32, kk = idx % 32;
            int i = i0 + r;
            has[kk][r] = (i < NN) ? g_ha[((size_t)b * NN + i) * HH + k0 + kk] : 0.f;
            int j = j0 + r;
            hbs[kk][r] = (j < NN) ? g_hb[((size_t)b * NN + j) * HH + k0 + kk] : 0.f;
        }
        if (tid < 32) {
            b1s[tid] = b1[k0 + tid];
            w2s[tid] = W2[k0 + tid];
        }
        __syncthreads();

        #pragma unroll
        for (int kk = 0; kk < 32; kk++) {
            float bias = b1s[kk];
            float w = w2s[kk];
            float a0 = has[kk][ty * 2];
            float a1 = has[kk][ty * 2 + 1];
            float c0 = hbs[kk][tx * 2];
            float c1 = hbs[kk][tx * 2 + 1];
            acc[0][0] += fmaxf(a0 + c0 + bias, 0.f) * w;
            acc[0][1] += fmaxf(a0 + c1 + bias, 0.f) * w;
            acc[1][0] += fmaxf(a1 + c0 + bias, 0.f) * w;
            acc[1][1] += fmaxf(a1 + c1 + bias, 0.f) * w;
        }
        __syncthreads();
    }

    float bb = b2[0];
    #pragma unroll
    for (int ii = 0; ii < 2; ii++) {
        #pragma unroll
        for (int jj = 0; jj < 2; jj++) {
            int i = i0 + ty * 2 + ii;
            int j = j0 + tx * 2 + jj;
            if (i < NN && j < NN) {
                float x = acc[ii][jj] + bb;
                out[(size_t)b * NN * NN + (size_t)i * NN + j] =
                    1.f / (1.f + expf(-x));
            }
        }
    }
}

// ---------------------------------------------------------------------------
// Launch
// inputs (metadata order): patch_tokens, boxes, W1, b1, W2, b2, img_h, img_w
// ---------------------------------------------------------------------------
extern "C" void kernel_launch(void* const* d_in, const int* in_sizes, int n_in,
                              void* d_out, int out_size) {
    const float* pt    = (const float*)d_in[0];
    const float* boxes = (const float*)d_in[1];
    const float* W1    = (const float*)d_in[2];
    const float* b1    = (const float*)d_in[3];
    const float* W2    = (const float*)d_in[4];
    const float* b2    = (const float*)d_in[5];
    const int*   imh   = (const int*)d_in[6];
    const int*   imw   = (const int*)d_in[7];
    float* out = (float*)d_out;

    pool_kernel<<<BN, 256>>>(pt, boxes, imh, imw);

    dim3 gg(HH / 64, (BN + 63) / 64, 2);   // (12, 13, 2)
    gemm_kernel<<<gg, 256>>>(W1);

    dim3 gp((NN + 31) / 32, (NN + 31) / 32, BB);  // (4, 4, 8)
    pair_kernel<<<gp, 256>>>(b1, W2, b2, out);
}

// round 2
// speedup vs baseline: 1.6046x; 1.6046x over previous
#include <cuda_runtime.h>
#include <cuda_bf16.h>
#include <math.h>

// Problem dims (fixed for this problem instance)
#define BB 8
#define NN 100
#define DD 768
#define HH 768
#define TT 577
#define TH 24
#define SW (TH+1)         // 25 (SAT side)
#define BN (BB*NN)        // 800

// Scratch (device globals; zero-initialized at module load — SAT border
// row/col 0 are never written, so they stay zero across graph replays)
__device__ float g_sat[BB * SW * SW * DD];
__device__ float g_pooled[BN * DD];
__device__ float g_ha[BN * HH];
__device__ float g_hb[BN * HH];

// ---------------------------------------------------------------------------
// Kernel 1a: row prefix sums.  thread = (b, y, d).  8*24*768 threads.
// g_sat[b][y+1][x+1][d] = sum_{x'<=x} feat[b][y][x'][d]
// ---------------------------------------------------------------------------
__global__ void sat_row_kernel(const float* __restrict__ pt) {
    int idx = blockIdx.x * 256 + threadIdx.x;
    int d = idx % DD;
    int rem = idx / DD;
    int y = rem % TH;
    int b = rem / TH;

    const float* base = pt + ((size_t)b * TT + 1 + (size_t)y * TH) * DD + d;
    float* srow = g_sat + (((size_t)b * SW + (y + 1)) * SW) * DD + d;

    float acc = 0.f;
    #pragma unroll
    for (int x = 0; x < TH; x++) {
        acc += base[(size_t)x * DD];
        srow[(size_t)(x + 1) * DD] = acc;
    }
}

// ---------------------------------------------------------------------------
// Kernel 1b: column prefix sums (in place).  thread = (b, x, d).
// ---------------------------------------------------------------------------
__global__ void sat_col_kernel() {
    int idx = blockIdx.x * 256 + threadIdx.x;
    int d = idx % DD;
    int rem = idx / DD;
    int x = rem % TH;         // maps to sat col x+1
    int b = rem / TH;

    float* scol = g_sat + (((size_t)b * SW) * SW + (x + 1)) * DD + d;

    float acc = 0.f;
    #pragma unroll
    for (int y = 1; y < SW; y++) {
        float* p = scol + (size_t)y * SW * DD;
        acc += *p;
        *p = acc;
    }
}

// ---------------------------------------------------------------------------
// Kernel 1c: ROI mean via 4-point SAT lookup.  thread = (bn, d).
// ---------------------------------------------------------------------------
__global__ void pool_lookup_kernel(const float* __restrict__ boxes,
                                   const int* __restrict__ imh,
                                   const int* __restrict__ imw) {
    int idx = blockIdx.x * 256 + threadIdx.x;
    int d = idx % DD;
    int bn = idx / DD;
    int b = bn / NN;

    const float* box = boxes + (size_t)bn * 4;
    float sizeW = (float)(*imw);
    float sizeH = (float)(*imh);

    // Replicate reference coordinate chain exactly in IEEE fp32
    int px1 = (int)floorf(floorf(box[0] * sizeW) / sizeW * (float)TH);
    int py1 = (int)floorf(floorf(box[1] * sizeH) / sizeH * (float)TH);
    int px2 = (int)floorf(floorf(box[2] * sizeW) / sizeW * (float)TH);
    int py2 = (int)floorf(floorf(box[3] * sizeH) / sizeH * (float)TH);
    px1 = min(max(px1, 0), TH - 1);
    py1 = min(max(py1, 0), TH - 1);
    px2 = min(max(px2, 1), TH);
    py2 = min(max(py2, 1), TH);
    if (px2 <= px1) px2 = px1 + 1;
    if (py2 <= py1) py2 = py1 + 1;

    float inv_cnt = 1.f / (float)((px2 - px1) * (py2 - py1));

    const float* S = g_sat + ((size_t)b * SW * SW) * DD + d;
    float s22 = S[((size_t)py2 * SW + px2) * DD];
    float s12 = S[((size_t)py1 * SW + px2) * DD];
    float s21 = S[((size_t)py2 * SW + px1) * DD];
    float s11 = S[((size_t)py1 * SW + px1) * DD];

    g_pooled[(size_t)bn * DD + d] = (s22 - s12 - s21 + s11) * inv_cnt;
}

// ---------------------------------------------------------------------------
// Kernel 2: GEMM  C[s] = pooled[800,768] @ W1[s*768:(s+1)*768, 768]
// 64x64x16 tiles, 256 threads, 4x4 microtile. grid = (12, 13, 2)
// ---------------------------------------------------------------------------
__global__ void gemm_kernel(const float* __restrict__ W1) {
    const int BM = 64, BNt = 64, BK = 16;
    int s = blockIdx.z;
    const float* Bmat = W1 + (size_t)s * DD * HH;   // [768,768] row-major
    float* C = s ? g_hb : g_ha;

    int m0 = blockIdx.y * BM;
    int n0 = blockIdx.x * BNt;

    __shared__ float As[BK][BM + 4];   // k-major, padded
    __shared__ float Bs[BK][BNt + 4];

    int tid = threadIdx.x;
    int tx = tid % 16, ty = tid / 16;

    float acc[4][4] = {};

    for (int k0 = 0; k0 < DD; k0 += BK) {
        #pragma unroll
        for (int t = 0; t < 4; t++) {
            int idx = tid + t * 256;
            int r = idx / BK, c = idx % BK;
            int m = m0 + r;
            float v = 0.f;
            if (m < BN) v = g_pooled[(size_t)m * DD + k0 + c];
            As[c][r] = v;
        }
        #pragma unroll
        for (int t = 0; t < 4; t++) {
            int idx = tid + t * 256;
            int r = idx / BNt, c = idx % BNt;
            Bs[r][c] = Bmat[(size_t)(k0 + r) * HH + n0 + c];
        }
        __syncthreads();

        #pragma unroll
        for (int kk = 0; kk < BK; kk++) {
            float4 a4 = *(const float4*)&As[kk][ty * 4];
            float4 b4 = *(const float4*)&Bs[kk][tx * 4];
            float a[4] = {a4.x, a4.y, a4.z, a4.w};
            float bv[4] = {b4.x, b4.y, b4.z, b4.w};
            #pragma unroll
            for (int i = 0; i < 4; i++)
                #pragma unroll
                for (int j = 0; j < 4; j++)
                    acc[i][j] += a[i] * bv[j];
        }
        __syncthreads();
    }

    #pragma unroll
    for (int i = 0; i < 4; i++) {
        int m = m0 + ty * 4 + i;
        if (m < BN) {
            #pragma unroll
            for (int j = 0; j < 4; j++)
                C[(size_t)m * HH + n0 + tx * 4 + j] = acc[i][j];
        }
    }
}

// ---------------------------------------------------------------------------
// Kernel 3: pairwise relu-dot + sigmoid.
// ---------------------------------------------------------------------------
__global__ void pair_kernel(const float* __restrict__ b1,
                            const float* __restrict__ W2,
                            const float* __restrict__ b2,
                            float* __restrict__ out) {
    int b = blockIdx.z;
    int i0 = blockIdx.y * 32;
    int j0 = blockIdx.x * 32;

    __shared__ float has[32][33];   // k-major
    __shared__ float hbs[32][33];
    __shared__ float b1s[32];
    __shared__ float w2s[32];

    int tid = threadIdx.x;
    int tx = tid % 16, ty = tid / 16;

    float acc[2][2] = {};

    for (int k0 = 0; k0 < HH; k0 += 32) {
        #pragma unroll
        for (int t = 0; t < 4; t++) {
            int idx = tid + t * 256;
            int r = idx / 32, kk = idx % 32;
            int i = i0 + r;
            has[kk][r] = (i < NN) ? g_ha[((size_t)b * NN + i) * HH + k0 + kk] : 0.f;
            int j = j0 + r;
            hbs[kk][r] = (j < NN) ? g_hb[((size_t)b * NN + j) * HH + k0 + kk] : 0.f;
        }
        if (tid < 32) {
            b1s[tid] = b1[k0 + tid];
            w2s[tid] = W2[k0 + tid];
        }
        __syncthreads();

        #pragma unroll
        for (int kk = 0; kk < 32; kk++) {
            float bias = b1s[kk];
            float w = w2s[kk];
            float a0 = has[kk][ty * 2];
            float a1 = has[kk][ty * 2 + 1];
            float c0 = hbs[kk][tx * 2];
            float c1 = hbs[kk][tx * 2 + 1];
            acc[0][0] += fmaxf(a0 + c0 + bias, 0.f) * w;
            acc[0][1] += fmaxf(a0 + c1 + bias, 0.f) * w;
            acc[1][0] += fmaxf(a1 + c0 + bias, 0.f) * w;
            acc[1][1] += fmaxf(a1 + c1 + bias, 0.f) * w;
        }
        __syncthreads();
    }

    float bb = b2[0];
    #pragma unroll
    for (int ii = 0; ii < 2; ii++) {
        #pragma unroll
        for (int jj = 0; jj < 2; jj++) {
            int i = i0 + ty * 2 + ii;
            int j = j0 + tx * 2 + jj;
            if (i < NN && j < NN) {
                float x = acc[ii][jj] + bb;
                out[(size_t)b * NN * NN + (size_t)i * NN + j] =
                    1.f / (1.f + expf(-x));
            }
        }
    }
}

// ---------------------------------------------------------------------------
// Launch.  inputs: patch_tokens, boxes, W1, b1, W2, b2, img_h, img_w
// ---------------------------------------------------------------------------
extern "C" void kernel_launch(void* const* d_in, const int* in_sizes, int n_in,
                              void* d_out, int out_size) {
    const float* pt    = (const float*)d_in[0];
    const float* boxes = (const float*)d_in[1];
    const float* W1    = (const float*)d_in[2];
    const float* b1    = (const float*)d_in[3];
    const float* W2    = (const float*)d_in[4];
    const float* b2    = (const float*)d_in[5];
    const int*   imh   = (const int*)d_in[6];
    const int*   imw   = (const int*)d_in[7];
    float* out = (float*)d_out;

    sat_row_kernel<<<(BB * TH * DD) / 256, 256>>>(pt);       // 576 blocks
    sat_col_kernel<<<(BB * TH * DD) / 256, 256>>>();         // 576 blocks
    pool_lookup_kernel<<<(BN * DD) / 256, 256>>>(boxes, imh, imw);  // 2400

    dim3 gg(HH / 64, (BN + 63) / 64, 2);   // (12, 13, 2)
    gemm_kernel<<<gg, 256>>>(W1);

    dim3 gp((NN + 31) / 32, (NN + 31) / 32, BB);  // (4, 4, 8)
    pair_kernel<<<gp, 256>>>(b1, W2, b2, out);
}

// round 3
// speedup vs baseline: 1.8116x; 1.1290x over previous
#include <cuda_runtime.h>
#include <cuda_bf16.h>
#include <math.h>

// Problem dims (fixed)
#define BB 8
#define NN 100
#define DD 768
#define HH 768
#define TT 577
#define TH 24
#define SW (TH+1)         // 25
#define BN (BB*NN)        // 800

// Scratch (device globals; zero-init — SAT border row/col never written)
__device__ float g_sat[BB * SW * SW * DD];
__device__ float g_pooled[BN * DD];
__device__ float g_ha[BN * HH];   // bias b1 folded in
__device__ float g_hb[BN * HH];

// ---------------- f32x2 packed helpers (Blackwell) -------------------------
__device__ __forceinline__ unsigned long long pack2(float lo, float hi) {
    unsigned long long r;
    asm("mov.b64 %0, {%1, %2};" : "=l"(r) : "f"(lo), "f"(hi));
    return r;
}
__device__ __forceinline__ unsigned long long bcast2(float v) {
    unsigned long long r;
    asm("mov.b64 %0, {%1, %1};" : "=l"(r) : "f"(v));
    return r;
}
__device__ __forceinline__ void ffma2(unsigned long long& d,
                                      unsigned long long a,
                                      unsigned long long b) {
    asm("fma.rn.f32x2 %0, %1, %2, %0;" : "+l"(d) : "l"(a), "l"(b));
}
__device__ __forceinline__ void unpack2(unsigned long long v, float& lo, float& hi) {
    asm("mov.b64 {%0, %1}, %2;" : "=f"(lo), "=f"(hi) : "l"(v));
}

// ---------------------------------------------------------------------------
// Kernel 1a: row prefix sums.  thread = (b, y, d).
// ---------------------------------------------------------------------------
__global__ void sat_row_kernel(const float* __restrict__ pt) {
    int idx = blockIdx.x * 256 + threadIdx.x;
    int d = idx % DD;
    int rem = idx / DD;
    int y = rem % TH;
    int b = rem / TH;

    const float* base = pt + ((size_t)b * TT + 1 + (size_t)y * TH) * DD + d;
    float* srow = g_sat + (((size_t)b * SW + (y + 1)) * SW) * DD + d;

    float acc = 0.f;
    #pragma unroll
    for (int x = 0; x < TH; x++) {
        acc += base[(size_t)x * DD];
        srow[(size_t)(x + 1) * DD] = acc;
    }
}

// ---------------------------------------------------------------------------
// Kernel 1b: column prefix sums (in place).  thread = (b, x, d).
// ---------------------------------------------------------------------------
__global__ void sat_col_kernel() {
    int idx = blockIdx.x * 256 + threadIdx.x;
    int d = idx % DD;
    int rem = idx / DD;
    int x = rem % TH;
    int b = rem / TH;

    float* scol = g_sat + (((size_t)b * SW) * SW + (x + 1)) * DD + d;

    float acc = 0.f;
    #pragma unroll
    for (int y = 1; y < SW; y++) {
        float* p = scol + (size_t)y * SW * DD;
        acc += *p;
        *p = acc;
    }
}

// ---------------------------------------------------------------------------
// Kernel 1c: ROI mean via 4-point SAT lookup.  thread = (bn, d).
// ---------------------------------------------------------------------------
__global__ void pool_lookup_kernel(const float* __restrict__ boxes,
                                   const int* __restrict__ imh,
                                   const int* __restrict__ imw) {
    int idx = blockIdx.x * 256 + threadIdx.x;
    int d = idx % DD;
    int bn = idx / DD;
    int b = bn / NN;

    const float* box = boxes + (size_t)bn * 4;
    float sizeW = (float)(*imw);
    float sizeH = (float)(*imh);

    int px1 = (int)floorf(floorf(box[0] * sizeW) / sizeW * (float)TH);
    int py1 = (int)floorf(floorf(box[1] * sizeH) / sizeH * (float)TH);
    int px2 = (int)floorf(floorf(box[2] * sizeW) / sizeW * (float)TH);
    int py2 = (int)floorf(floorf(box[3] * sizeH) / sizeH * (float)TH);
    px1 = min(max(px1, 0), TH - 1);
    py1 = min(max(py1, 0), TH - 1);
    px2 = min(max(px2, 1), TH);
    py2 = min(max(py2, 1), TH);
    if (px2 <= px1) px2 = px1 + 1;
    if (py2 <= py1) py2 = py1 + 1;

    float inv_cnt = 1.f / (float)((px2 - px1) * (py2 - py1));

    const float* S = g_sat + ((size_t)b * SW * SW) * DD + d;
    float s22 = S[((size_t)py2 * SW + px2) * DD];
    float s12 = S[((size_t)py1 * SW + px2) * DD];
    float s21 = S[((size_t)py2 * SW + px1) * DD];
    float s11 = S[((size_t)py1 * SW + px1) * DD];

    g_pooled[(size_t)bn * DD + d] = (s22 - s12 - s21 + s11) * inv_cnt;
}

// ---------------------------------------------------------------------------
// Kernel 2: GEMM with FFMA2.  C = pooled[800,768] @ Blogical[768,1536]
// Blogical cols 0..767 -> W1 rows 0..767 (ha, + b1 bias); 768..1535 -> W1
// rows 768..1535 (hb).  Tiles 64x32, 128 threads, 4x4 micro, BK=16.
// grid = (48, 13) = 624 CTAs.
// ---------------------------------------------------------------------------
#define GM 64
#define GN 32
#define GK 16
__global__ void gemm_kernel(const float* __restrict__ W1,
                            const float* __restrict__ b1) {
    int n0g = blockIdx.x * GN;
    int m0 = blockIdx.y * GM;
    int s = (n0g >= HH) ? 1 : 0;
    int n0 = s ? (n0g - HH) : n0g;
    const float* Bbase = W1 + (size_t)s * DD * HH;
    float* C = s ? g_hb : g_ha;

    __shared__ float As[GK][GM + 4];   // k-major
    __shared__ float Bs[GK][GN + 4];

    int tid = threadIdx.x;             // 128
    int tx = tid % 8;                  // n/4  (0..7)
    int ty = tid / 8;                  // m/4  (0..15)

    unsigned long long acc[4][2] = {};  // 4 m-rows x 2 f32x2 (4 n-cols)

    for (int k0 = 0; k0 < DD; k0 += GK) {
        // A tile 64x16 -> transposed As[k][m]
        #pragma unroll
        for (int t = 0; t < 8; t++) {
            int idx = tid + t * 128;
            int r = idx / GK, c = idx % GK;
            int m = m0 + r;
            As[c][r] = (m < BN) ? g_pooled[(size_t)m * DD + k0 + c] : 0.f;
        }
        // B tile 16x32
        #pragma unroll
        for (int t = 0; t < 4; t++) {
            int idx = tid + t * 128;
            int r = idx / GN, c = idx % GN;
            Bs[r][c] = Bbase[(size_t)(k0 + r) * HH + n0 + c];
        }
        __syncthreads();

        #pragma unroll
        for (int kk = 0; kk < GK; kk++) {
            float4 a4 = *(const float4*)&As[kk][ty * 4];
            float4 b4 = *(const float4*)&Bs[kk][tx * 4];
            unsigned long long bp0 = pack2(b4.x, b4.y);
            unsigned long long bp1 = pack2(b4.z, b4.w);
            unsigned long long ap;
            ap = bcast2(a4.x); ffma2(acc[0][0], ap, bp0); ffma2(acc[0][1], ap, bp1);
            ap = bcast2(a4.y); ffma2(acc[1][0], ap, bp0); ffma2(acc[1][1], ap, bp1);
            ap = bcast2(a4.z); ffma2(acc[2][0], ap, bp0); ffma2(acc[2][1], ap, bp1);
            ap = bcast2(a4.w); ffma2(acc[3][0], ap, bp0); ffma2(acc[3][1], ap, bp1);
        }
        __syncthreads();
    }

    // Epilogue: unpack, fold b1 into ha half, guarded store
    float bias[4] = {0.f, 0.f, 0.f, 0.f};
    if (!s) {
        #pragma unroll
        for (int j = 0; j < 4; j++) bias[j] = b1[n0 + tx * 4 + j];
    }
    #pragma unroll
    for (int i = 0; i < 4; i++) {
        int m = m0 + ty * 4 + i;
        if (m < BN) {
            float v[4];
            unpack2(acc[i][0], v[0], v[1]);
            unpack2(acc[i][1], v[2], v[3]);
            float* cp = C + (size_t)m * HH + n0 + tx * 4;
            #pragma unroll
            for (int j = 0; j < 4; j++) cp[j] = v[j] + bias[j];
        }
    }
}

// ---------------------------------------------------------------------------
// Kernel 3: pairwise relu-dot + sigmoid.  32x32 tiles, 256 thr, 2x2 micro,
// k-chunk 64, row-major smem, 4-wide k unroll.  bias already folded into ha.
// ---------------------------------------------------------------------------
#define KC 64
__global__ void pair_kernel(const float* __restrict__ W2,
                            const float* __restrict__ b2,
                            float* __restrict__ out) {
    int b = blockIdx.z;
    int i0 = blockIdx.y * 32;
    int j0 = blockIdx.x * 32;

    __shared__ float has[32][KC + 4];   // row-major: has[row][kk]
    __shared__ float hbs[32][KC + 4];
    __shared__ float w2s[KC];

    int tid = threadIdx.x;
    int tx = tid % 16, ty = tid / 16;

    float acc[2][2] = {};

    for (int k0 = 0; k0 < HH; k0 += KC) {
        // fill: 32 rows x 64 cols per array = 512 float4 / 256 threads = 2
        #pragma unroll
        for (int t = 0; t < 2; t++) {
            int idx = tid + t * 256;          // 0..511
            int r = idx / 16, c4 = idx % 16;  // row, float4-col
            int i = i0 + r;
            float4 va = make_float4(0.f, 0.f, 0.f, 0.f);
            if (i < NN) va = *(const float4*)&g_ha[((size_t)b * NN + i) * HH + k0 + c4 * 4];
            *(float4*)&has[r][c4 * 4] = va;
            int j = j0 + r;
            float4 vb = make_float4(0.f, 0.f, 0.f, 0.f);
            if (j < NN) vb = *(const float4*)&g_hb[((size_t)b * NN + j) * HH + k0 + c4 * 4];
            *(float4*)&hbs[r][c4 * 4] = vb;
        }
        if (tid < KC / 4)
            *(float4*)&w2s[tid * 4] = *(const float4*)&W2[k0 + tid * 4];
        __syncthreads();

        #pragma unroll
        for (int kk = 0; kk < KC; kk += 4) {
            float4 a0 = *(const float4*)&has[ty * 2][kk];
            float4 a1 = *(const float4*)&has[ty * 2 + 1][kk];
            float4 c0 = *(const float4*)&hbs[tx * 2][kk];
            float4 c1 = *(const float4*)&hbs[tx * 2 + 1][kk];
            float4 w  = *(const float4*)&w2s[kk];

            acc[0][0] += fmaxf(a0.x + c0.x, 0.f) * w.x;
            acc[0][1] += fmaxf(a0.x + c1.x, 0.f) * w.x;
            acc[1][0] += fmaxf(a1.x + c0.x, 0.f) * w.x;
            acc[1][1] += fmaxf(a1.x + c1.x, 0.f) * w.x;

            acc[0][0] += fmaxf(a0.y + c0.y, 0.f) * w.y;
            acc[0][1] += fmaxf(a0.y + c1.y, 0.f) * w.y;
            acc[1][0] += fmaxf(a1.y + c0.y, 0.f) * w.y;
            acc[1][1] += fmaxf(a1.y + c1.y, 0.f) * w.y;

            acc[0][0] += fmaxf(a0.z + c0.z, 0.f) * w.z;
            acc[0][1] += fmaxf(a0.z + c1.z, 0.f) * w.z;
            acc[1][0] += fmaxf(a1.z + c0.z, 0.f) * w.z;
            acc[1][1] += fmaxf(a1.z + c1.z, 0.f) * w.z;

            acc[0][0] += fmaxf(a0.w + c0.w, 0.f) * w.w;
            acc[0][1] += fmaxf(a0.w + c1.w, 0.f) * w.w;
            acc[1][0] += fmaxf(a1.w + c0.w, 0.f) * w.w;
            acc[1][1] += fmaxf(a1.w + c1.w, 0.f) * w.w;
        }
        __syncthreads();
    }

    float bb = b2[0];
    #pragma unroll
    for (int ii = 0; ii < 2; ii++) {
        #pragma unroll
        for (int jj = 0; jj < 2; jj++) {
            int i = i0 + ty * 2 + ii;
            int j = j0 + tx * 2 + jj;
            if (i < NN && j < NN) {
                float x = acc[ii][jj] + bb;
                out[(size_t)b * NN * NN + (size_t)i * NN + j] =
                    1.f / (1.f + expf(-x));
            }
        }
    }
}

// ---------------------------------------------------------------------------
// Launch.  inputs: patch_tokens, boxes, W1, b1, W2, b2, img_h, img_w
// ---------------------------------------------------------------------------
extern "C" void kernel_launch(void* const* d_in, const int* in_sizes, int n_in,
                              void* d_out, int out_size) {
    const float* pt    = (const float*)d_in[0];
    const float* boxes = (const float*)d_in[1];
    const float* W1    = (const float*)d_in[2];
    const float* b1    = (const float*)d_in[3];
    const float* W2    = (const float*)d_in[4];
    const float* b2    = (const float*)d_in[5];
    const int*   imh   = (const int*)d_in[6];
    const int*   imw   = (const int*)d_in[7];
    float* out = (float*)d_out;

    sat_row_kernel<<<(BB * TH * DD) / 256, 256>>>(pt);
    sat_col_kernel<<<(BB * TH * DD) / 256, 256>>>();
    pool_lookup_kernel<<<(BN * DD) / 256, 256>>>(boxes, imh, imw);

    dim3 gg(2 * HH / GN, (BN + GM - 1) / GM);   // (48, 13)
    gemm_kernel<<<gg, 128>>>(W1, b1);

    dim3 gp((NN + 31) / 32, (NN + 31) / 32, BB);  // (4, 4, 8)
    pair_kernel<<<gp, 256>>>(W2, b2, out);
}

// round 6
// speedup vs baseline: 2.6289x; 1.4511x over previous
#include <cuda_runtime.h>
#include <cuda_bf16.h>
#include <math.h>
#include <stdint.h>

// Problem dims (fixed)
#define BB 8
#define NN 100
#define DD 768
#define HH 768
#define TT 577
#define TH 24
#define SW (TH+1)         // 25
#define BN (BB*NN)        // 800
#define MPAD 896          // zero-padded A rows (covers 13*64=832)

// ---------------- scratch (device globals; zero-initialized) ---------------
__device__ float g_sat[BB * SW * SW * DD];
__device__ float g_ha[BN * HH];   // bias b1 folded in
__device__ float g_hb[BN * HH];
// bf16 split operands (16B-aligned)
__device__ uint4 g_pA_hi[MPAD * DD / 8];     // [896][768] bf16, rows >=800 zero
__device__ uint4 g_pA_lo[MPAD * DD / 8];
__device__ uint4 g_wt_hi[2 * HH * DD / 8];   // [1536][768] bf16 (row n, col k)
__device__ uint4 g_wt_lo[2 * HH * DD / 8];

// ---------------- helpers --------------------------------------------------
__device__ __forceinline__ uint32_t smem_u32(const void* p) {
    uint32_t a;
    asm("{ .reg .u64 t; cvta.to.shared.u64 t, %1; cvt.u32.u64 %0, t; }"
        : "=r"(a) : "l"(p));
    return a;
}

__device__ __forceinline__ void ldm_x4(uint32_t* r, uint32_t addr) {
    asm volatile("ldmatrix.sync.aligned.m8n8.x4.shared.b16 {%0,%1,%2,%3}, [%4];"
                 : "=r"(r[0]), "=r"(r[1]), "=r"(r[2]), "=r"(r[3]) : "r"(addr));
}
__device__ __forceinline__ void ldm_x2(uint32_t* r, uint32_t addr) {
    asm volatile("ldmatrix.sync.aligned.m8n8.x2.shared.b16 {%0,%1}, [%2];"
                 : "=r"(r[0]), "=r"(r[1]) : "r"(addr));
}
__device__ __forceinline__ void mma16816(float* c, const uint32_t* a,
                                         const uint32_t* b) {
    asm volatile(
        "mma.sync.aligned.m16n8k16.row.col.f32.bf16.bf16.f32 "
        "{%0,%1,%2,%3}, {%4,%5,%6,%7}, {%8,%9}, {%0,%1,%2,%3};"
        : "+f"(c[0]), "+f"(c[1]), "+f"(c[2]), "+f"(c[3])
        : "r"(a[0]), "r"(a[1]), "r"(a[2]), "r"(a[3]), "r"(b[0]), "r"(b[1]));
}

// ---------------------------------------------------------------------------
// Kernel 1a: row prefix sums.
// ---------------------------------------------------------------------------
__global__ void sat_row_kernel(const float* __restrict__ pt) {
    int idx = blockIdx.x * 256 + threadIdx.x;
    int d = idx % DD;
    int rem = idx / DD;
    int y = rem % TH;
    int b = rem / TH;

    const float* base = pt + ((size_t)b * TT + 1 + (size_t)y * TH) * DD + d;
    float* srow = g_sat + (((size_t)b * SW + (y + 1)) * SW) * DD + d;

    float acc = 0.f;
    #pragma unroll
    for (int x = 0; x < TH; x++) {
        acc += base[(size_t)x * DD];
        srow[(size_t)(x + 1) * DD] = acc;
    }
}

// ---------------------------------------------------------------------------
// Kernel 1b: column prefix sums (in place).
// ---------------------------------------------------------------------------
__global__ void sat_col_kernel() {
    int idx = blockIdx.x * 256 + threadIdx.x;
    int d = idx % DD;
    int rem = idx / DD;
    int x = rem % TH;
    int b = rem / TH;

    float* scol = g_sat + (((size_t)b * SW) * SW + (x + 1)) * DD + d;

    float acc = 0.f;
    #pragma unroll
    for (int y = 1; y < SW; y++) {
        float* p = scol + (size_t)y * SW * DD;
        acc += *p;
        *p = acc;
    }
}

// ---------------------------------------------------------------------------
// Kernel 1c: ROI mean via SAT lookup -> bf16 hi/lo split operand A.
// ---------------------------------------------------------------------------
__global__ void pool_lookup_kernel(const float* __restrict__ boxes,
                                   const int* __restrict__ imh,
                                   const int* __restrict__ imw) {
    int idx = blockIdx.x * 256 + threadIdx.x;
    int d = idx % DD;
    int bn = idx / DD;
    int b = bn / NN;

    const float* box = boxes + (size_t)bn * 4;
    float sizeW = (float)(*imw);
    float sizeH = (float)(*imh);

    int px1 = (int)floorf(floorf(box[0] * sizeW) / sizeW * (float)TH);
    int py1 = (int)floorf(floorf(box[1] * sizeH) / sizeH * (float)TH);
    int px2 = (int)floorf(floorf(box[2] * sizeW) / sizeW * (float)TH);
    int py2 = (int)floorf(floorf(box[3] * sizeH) / sizeH * (float)TH);
    px1 = min(max(px1, 0), TH - 1);
    py1 = min(max(py1, 0), TH - 1);
    px2 = min(max(px2, 1), TH);
    py2 = min(max(py2, 1), TH);
    if (px2 <= px1) px2 = px1 + 1;
    if (py2 <= py1) py2 = py1 + 1;

    float inv_cnt = 1.f / (float)((px2 - px1) * (py2 - py1));

    const float* S = g_sat + ((size_t)b * SW * SW) * DD + d;
    float s22 = S[((size_t)py2 * SW + px2) * DD];
    float s12 = S[((size_t)py1 * SW + px2) * DD];
    float s21 = S[((size_t)py2 * SW + px1) * DD];
    float s11 = S[((size_t)py1 * SW + px1) * DD];

    float p = (s22 - s12 - s21 + s11) * inv_cnt;
    __nv_bfloat16 hi = __float2bfloat16(p);
    __nv_bfloat16 lo = __float2bfloat16(p - __bfloat162float(hi));
    ((__nv_bfloat16*)g_pA_hi)[(size_t)bn * DD + d] = hi;
    ((__nv_bfloat16*)g_pA_lo)[(size_t)bn * DD + d] = lo;
}

// ---------------------------------------------------------------------------
// Kernel 1d: transpose + bf16 hi/lo split of W1.
// Wt[row = s*768 + n][col = k] = W1[s*768 + k][n].   grid (24,24,2), 256 thr.
// ---------------------------------------------------------------------------
__global__ void convert_w_kernel(const float* __restrict__ W1) {
    __shared__ float tile[32][33];
    int s = blockIdx.z;
    int k0 = blockIdx.x * 32;
    int n0 = blockIdx.y * 32;
    int tx = threadIdx.x % 32, ty = threadIdx.x / 32;   // ty 0..7

    #pragma unroll
    for (int j = 0; j < 4; j++) {
        int k = k0 + ty + j * 8;
        tile[ty + j * 8][tx] = W1[((size_t)(s * DD + k)) * HH + n0 + tx];
    }
    __syncthreads();

    __nv_bfloat16* Whi = (__nv_bfloat16*)g_wt_hi;
    __nv_bfloat16* Wlo = (__nv_bfloat16*)g_wt_lo;
    #pragma unroll
    for (int j = 0; j < 4; j++) {
        int n = n0 + ty + j * 8;
        float v = tile[tx][ty + j * 8];
        __nv_bfloat16 hi = __float2bfloat16(v);
        __nv_bfloat16 lo = __float2bfloat16(v - __bfloat162float(hi));
        size_t o = ((size_t)(s * HH + n)) * DD + k0 + tx;
        Whi[o] = hi;
        Wlo[o] = lo;
    }
}

// ---------------------------------------------------------------------------
// Kernel 2: HMMA (mma.sync) bf16 split GEMM.
// C[m,n] = pooled[800,768] @ Wt[1536,768]^T   via 3 MMAs per product
// (hi*hi + lo*hi + hi*lo).  CTA tile 64x64, 4 warps (each 32x32),
// K-chunk 32, register prefetch.  grid = (24, 13) = 312 CTAs.
// ---------------------------------------------------------------------------
#define KCH 32
#define NCHUNK (DD / KCH)     // 24
#define PITCHB 80             // 32 bf16 (64B) + 16B pad per smem row
#define T_AHI 0
#define T_ALO 5120
#define T_BHI 10240
#define T_BLO 15360

__global__ void __launch_bounds__(128)
hmma_gemm_kernel(const float* __restrict__ b1) {
    __shared__ __align__(16) char smem[4 * 5120];
    uint32_t sb = smem_u32(smem);

    int tid = threadIdx.x;
    int wid = tid / 32, lid = tid % 32;
    int wy = wid / 2, wx = wid % 2;          // warp tile: (wy*32, wx*32)

    int nt = blockIdx.x;                     // 0..23
    int m0 = blockIdx.y * 64;
    int nrow0 = nt * 64;                     // row base into Wt

    const char* Ahi = (const char*)g_pA_hi;
    const char* Alo = (const char*)g_pA_lo;
    const char* Bhi = (const char*)g_wt_hi;
    const char* Blo = (const char*)g_wt_lo;

    // per-thread gmem granule coords (2 granule-iters)
    int r0 = tid / 4 * 2, g0 = tid % 4;      // rows r0, r0+... use idx scheme:
    // idx = tid + t*128 -> r = idx/4, g = idx%4
    float acc[2][4][4] = {};                 // [m-frag][n-frag][4]

    uint4 pa_hi[2], pa_lo[2], pb_hi[2], pb_lo[2];
    (void)r0; (void)g0;

    // prefetch chunk 0
    {
        #pragma unroll
        for (int t = 0; t < 2; t++) {
            int idx = tid + t * 128;
            int r = idx >> 2, g = idx & 3;
            size_t oa = ((size_t)(m0 + r) * DD) * 2 + (size_t)g * 16;
            size_t ob = ((size_t)(nrow0 + r) * DD) * 2 + (size_t)g * 16;
            pa_hi[t] = *(const uint4*)(Ahi + oa);
            pa_lo[t] = *(const uint4*)(Alo + oa);
            pb_hi[t] = *(const uint4*)(Bhi + ob);
            pb_lo[t] = *(const uint4*)(Blo + ob);
        }
    }

    // ldmatrix lane address components
    int la_row = lid % 16, la_blk = lid / 16;           // A: x4
    int lb_row = lid % 8, lb_blk = (lid / 8) & 1;       // B: x2 (lanes 0-15)

    for (int ch = 0; ch < NCHUNK; ch++) {
        // store prefetched chunk to smem
        #pragma unroll
        for (int t = 0; t < 2; t++) {
            int idx = tid + t * 128;
            int r = idx >> 2, g = idx & 3;
            uint32_t off = (uint32_t)(r * PITCHB + g * 16);
            *(uint4*)(smem + T_AHI + off) = pa_hi[t];
            *(uint4*)(smem + T_ALO + off) = pa_lo[t];
            *(uint4*)(smem + T_BHI + off) = pb_hi[t];
            *(uint4*)(smem + T_BLO + off) = pb_lo[t];
        }
        __syncthreads();

        // prefetch next chunk (overlaps compute)
        if (ch + 1 < NCHUNK) {
            int kb = (ch + 1) * KCH;
            #pragma unroll
            for (int t = 0; t < 2; t++) {
                int idx = tid + t * 128;
                int r = idx >> 2, g = idx & 3;
                size_t oa = ((size_t)(m0 + r) * DD + kb) * 2 + (size_t)g * 16;
                size_t ob = ((size_t)(nrow0 + r) * DD + kb) * 2 + (size_t)g * 16;
                pa_hi[t] = *(const uint4*)(Ahi + oa);
                pa_lo[t] = *(const uint4*)(Alo + oa);
                pb_hi[t] = *(const uint4*)(Bhi + ob);
                pb_lo[t] = *(const uint4*)(Blo + ob);
            }
        }

        // compute: 2 k-steps of 16
        #pragma unroll
        for (int ks = 0; ks < 2; ks++) {
            int kofs = ks * 16;
            uint32_t ahi[2][4], alo[2][4], bhi[4][2], blo[4][2];

            #pragma unroll
            for (int mf = 0; mf < 2; mf++) {
                uint32_t ad = sb + (uint32_t)((wy * 32 + mf * 16 + la_row) * PITCHB
                                              + (kofs + la_blk * 8) * 2);
                ldm_x4(ahi[mf], T_AHI + ad);
                ldm_x4(alo[mf], T_ALO + ad);
            }
            #pragma unroll
            for (int nf = 0; nf < 4; nf++) {
                uint32_t bd = sb + (uint32_t)((wx * 32 + nf * 8 + lb_row) * PITCHB
                                              + (kofs + lb_blk * 8) * 2);
                ldm_x2(bhi[nf], T_BHI + bd);
                ldm_x2(blo[nf], T_BLO + bd);
            }

            #pragma unroll
            for (int mf = 0; mf < 2; mf++) {
                #pragma unroll
                for (int nf = 0; nf < 4; nf++) {
                    mma16816(acc[mf][nf], ahi[mf], bhi[nf]);
                    mma16816(acc[mf][nf], alo[mf], bhi[nf]);
                    mma16816(acc[mf][nf], ahi[mf], blo[nf]);
                }
            }
        }
        __syncthreads();
    }

    // Epilogue: fold b1 for the ha half, store float2 pairs
    bool is_ha = (nt < 12);
    float* C = is_ha ? g_ha : g_hb;
    int n0 = (is_ha ? nt : nt - 12) * 64;

    #pragma unroll
    for (int mf = 0; mf < 2; mf++) {
        #pragma unroll
        for (int nf = 0; nf < 4; nf++) {
            int m = m0 + wy * 32 + mf * 16 + lid / 4;
            int n = n0 + wx * 32 + nf * 8 + 2 * (lid % 4);
            float2 bia = make_float2(0.f, 0.f);
            if (is_ha) bia = *(const float2*)(b1 + n);
            if (m < BN) {
                float2 v = make_float2(acc[mf][nf][0] + bia.x,
                                       acc[mf][nf][1] + bia.y);
                *(float2*)(C + (size_t)m * HH + n) = v;
            }
            if (m + 8 < BN) {
                float2 v = make_float2(acc[mf][nf][2] + bia.x,
                                       acc[mf][nf][3] + bia.y);
                *(float2*)(C + (size_t)(m + 8) * HH + n) = v;
            }
        }
    }
}

// ---------------------------------------------------------------------------
// Kernel 3: pairwise relu-dot + sigmoid (round-3 version).
// ---------------------------------------------------------------------------
#define KC 64
__global__ void pair_kernel(const float* __restrict__ W2,
                            const float* __restrict__ b2,
                            float* __restrict__ out) {
    int b = blockIdx.z;
    int i0 = blockIdx.y * 32;
    int j0 = blockIdx.x * 32;

    __shared__ float has[32][KC + 4];
    __shared__ float hbs[32][KC + 4];
    __shared__ float w2s[KC];

    int tid = threadIdx.x;
    int tx = tid % 16, ty = tid / 16;

    float acc[2][2] = {};

    for (int k0 = 0; k0 < HH; k0 += KC) {
        #pragma unroll
        for (int t = 0; t < 2; t++) {
            int idx = tid + t * 256;
            int r = idx / 16, c4 = idx % 16;
            int i = i0 + r;
            float4 va = make_float4(0.f, 0.f, 0.f, 0.f);
            if (i < NN) va = *(const float4*)&g_ha[((size_t)b * NN + i) * HH + k0 + c4 * 4];
            *(float4*)&has[r][c4 * 4] = va;
            int j = j0 + r;
            float4 vb = make_float4(0.f, 0.f, 0.f, 0.f);
            if (j < NN) vb = *(const float4*)&g_hb[((size_t)b * NN + j) * HH + k0 + c4 * 4];
            *(float4*)&hbs[r][c4 * 4] = vb;
        }
        if (tid < KC / 4)
            *(float4*)&w2s[tid * 4] = *(const float4*)&W2[k0 + tid * 4];
        __syncthreads();

        #pragma unroll
        for (int kk = 0; kk < KC; kk += 4) {
            float4 a0 = *(const float4*)&has[ty * 2][kk];
            float4 a1 = *(const float4*)&has[ty * 2 + 1][kk];
            float4 c0 = *(const float4*)&hbs[tx * 2][kk];
            float4 c1 = *(const float4*)&hbs[tx * 2 + 1][kk];
            float4 w  = *(const float4*)&w2s[kk];

            acc[0][0] += fmaxf(a0.x + c0.x, 0.f) * w.x;
            acc[0][1] += fmaxf(a0.x + c1.x, 0.f) * w.x;
            acc[1][0] += fmaxf(a1.x + c0.x, 0.f) * w.x;
            acc[1][1] += fmaxf(a1.x + c1.x, 0.f) * w.x;

            acc[0][0] += fmaxf(a0.y + c0.y, 0.f) * w.y;
            acc[0][1] += fmaxf(a0.y + c1.y, 0.f) * w.y;
            acc[1][0] += fmaxf(a1.y + c0.y, 0.f) * w.y;
            acc[1][1] += fmaxf(a1.y + c1.y, 0.f) * w.y;

            acc[0][0] += fmaxf(a0.z + c0.z, 0.f) * w.z;
            acc[0][1] += fmaxf(a0.z + c1.z, 0.f) * w.z;
            acc[1][0] += fmaxf(a1.z + c0.z, 0.f) * w.z;
            acc[1][1] += fmaxf(a1.z + c1.z, 0.f) * w.z;

            acc[0][0] += fmaxf(a0.w + c0.w, 0.f) * w.w;
            acc[0][1] += fmaxf(a0.w + c1.w, 0.f) * w.w;
            acc[1][0] += fmaxf(a1.w + c0.w, 0.f) * w.w;
            acc[1][1] += fmaxf(a1.w + c1.w, 0.f) * w.w;
        }
        __syncthreads();
    }

    float bb = b2[0];
    #pragma unroll
    for (int ii = 0; ii < 2; ii++) {
        #pragma unroll
        for (int jj = 0; jj < 2; jj++) {
            int i = i0 + ty * 2 + ii;
            int j = j0 + tx * 2 + jj;
            if (i < NN && j < NN) {
                float x = acc[ii][jj] + bb;
                out[(size_t)b * NN * NN + (size_t)i * NN + j] =
                    1.f / (1.f + expf(-x));
            }
        }
    }
}

// ---------------------------------------------------------------------------
// Launch.  inputs: patch_tokens, boxes, W1, b1, W2, b2, img_h, img_w
// ---------------------------------------------------------------------------
extern "C" void kernel_launch(void* const* d_in, const int* in_sizes, int n_in,
                              void* d_out, int out_size) {
    const float* pt    = (const float*)d_in[0];
    const float* boxes = (const float*)d_in[1];
    const float* W1    = (const float*)d_in[2];
    const float* b1    = (const float*)d_in[3];
    const float* W2    = (const float*)d_in[4];
    const float* b2    = (const float*)d_in[5];
    const int*   imh   = (const int*)d_in[6];
    const int*   imw   = (const int*)d_in[7];
    float* out = (float*)d_out;

    sat_row_kernel<<<(BB * TH * DD) / 256, 256>>>(pt);
    sat_col_kernel<<<(BB * TH * DD) / 256, 256>>>();
    pool_lookup_kernel<<<(BN * DD) / 256, 256>>>(boxes, imh, imw);

    dim3 gw(DD / 32, HH / 32, 2);     // (24, 24, 2)
    convert_w_kernel<<<gw, 256>>>(W1);

    dim3 gg(2 * HH / 64, (BN + 63) / 64);   // (24, 13) = 312 CTAs
    hmma_gemm_kernel<<<gg, 128>>>(b1);

    dim3 gp((NN + 31) / 32, (NN + 31) / 32, BB);
    pair_kernel<<<gp, 256>>>(W2, b2, out);
}

// round 7
// speedup vs baseline: 2.6795x; 1.0192x over previous
#include <cuda_runtime.h>
#include <cuda_bf16.h>
#include <math.h>
#include <stdint.h>

// Problem dims (fixed)
#define BB 8
#define NN 100
#define DD 768
#define HH 768
#define TT 577
#define TH 24
#define SW (TH+1)         // 25
#define BN (BB*NN)        // 800
#define MPAD 896          // zero-padded A rows (covers 13*64=832)

// ---------------- scratch (device globals; zero-initialized) ---------------
__device__ float g_sat[BB * SW * SW * DD];
__device__ float g_ha[BN * HH];   // bias b1 folded in
__device__ float g_hb[BN * HH];
// bf16 split operands (16B-aligned)
__device__ uint4 g_pA_hi[MPAD * DD / 8];     // [896][768] bf16, rows >=800 zero
__device__ uint4 g_pA_lo[MPAD * DD / 8];
__device__ uint4 g_wt_hi[2 * HH * DD / 8];   // [1536][768] bf16 (row n, col k)
__device__ uint4 g_wt_lo[2 * HH * DD / 8];

// ---------------- helpers --------------------------------------------------
typedef unsigned long long ull;

__device__ __forceinline__ uint32_t smem_u32(const void* p) {
    uint32_t a;
    asm("{ .reg .u64 t; cvta.to.shared.u64 t, %1; cvt.u32.u64 %0, t; }"
        : "=r"(a) : "l"(p));
    return a;
}
__device__ __forceinline__ void ldm_x4(uint32_t* r, uint32_t addr) {
    asm volatile("ldmatrix.sync.aligned.m8n8.x4.shared.b16 {%0,%1,%2,%3}, [%4];"
                 : "=r"(r[0]), "=r"(r[1]), "=r"(r[2]), "=r"(r[3]) : "r"(addr));
}
__device__ __forceinline__ void ldm_x2(uint32_t* r, uint32_t addr) {
    asm volatile("ldmatrix.sync.aligned.m8n8.x2.shared.b16 {%0,%1}, [%2];"
                 : "=r"(r[0]), "=r"(r[1]) : "r"(addr));
}
__device__ __forceinline__ void mma16816(float* c, const uint32_t* a,
                                         const uint32_t* b) {
    asm volatile(
        "mma.sync.aligned.m16n8k16.row.col.f32.bf16.bf16.f32 "
        "{%0,%1,%2,%3}, {%4,%5,%6,%7}, {%8,%9}, {%0,%1,%2,%3};"
        : "+f"(c[0]), "+f"(c[1]), "+f"(c[2]), "+f"(c[3])
        : "r"(a[0]), "r"(a[1]), "r"(a[2]), "r"(a[3]), "r"(b[0]), "r"(b[1]));
}

// packed f32x2 (Blackwell)
__device__ __forceinline__ ull pack2(float lo, float hi) {
    ull r;
    asm("mov.b64 %0, {%1, %2};" : "=l"(r) : "f"(lo), "f"(hi));
    return r;
}
__device__ __forceinline__ void unpack2(ull v, float& lo, float& hi) {
    asm("mov.b64 {%0, %1}, %2;" : "=f"(lo), "=f"(hi) : "l"(v));
}
__device__ __forceinline__ ull add2(ull a, ull b) {
    ull r;
    asm("add.rn.f32x2 %0, %1, %2;" : "=l"(r) : "l"(a), "l"(b));
    return r;
}
__device__ __forceinline__ void fma2(ull& d, ull a, ull b) {
    asm("fma.rn.f32x2 %0, %1, %2, %0;" : "+l"(d) : "l"(a), "l"(b));
}
__device__ __forceinline__ ull relu2(ull s) {
    float lo, hi;
    unpack2(s, lo, hi);
    lo = fmaxf(lo, 0.f);
    hi = fmaxf(hi, 0.f);
    return pack2(lo, hi);
}

// ---------------------------------------------------------------------------
// Kernel 1: fused SAT (row prefix + col prefix) per (b, 32-d chunk).
// smem plane [25][25][32] f32 = 80 KB.  grid (8, 24), 256 threads.
// Accumulation order identical to the previous two-pass version.
// ---------------------------------------------------------------------------
#define DCH 32
__global__ void sat_fused_kernel(const float* __restrict__ pt) {
    extern __shared__ float sp[];     // [y][x][d] = [25][25][32]
    int b = blockIdx.x;
    int dc = blockIdx.y;
    int tid = threadIdx.x;
    int d = tid % DCH;
    int grp = tid / DCH;              // 0..7
    int dbase = dc * DCH;

    const float* base = pt + ((size_t)b * TT + 1) * DD + dbase + d;

    // row prefix: each thread owns 3 y-rows
    #pragma unroll
    for (int yy = 0; yy < 3; yy++) {
        int y = grp + yy * 8;
        const float* rp = base + (size_t)y * TH * DD;
        float* srow = sp + (size_t)(y + 1) * SW * DCH + d;
        float acc = 0.f;
        #pragma unroll
        for (int x = 0; x < TH; x++) {
            acc += rp[(size_t)x * DD];
            srow[(x + 1) * DCH] = acc;
        }
    }
    __syncthreads();

    // col prefix + global store: each thread owns 3 x-cols
    float* gs = g_sat + ((size_t)b * SW * SW) * DD + dbase + d;
    #pragma unroll
    for (int xx = 0; xx < 3; xx++) {
        int x = grp + xx * 8;         // sat col x+1
        float acc = 0.f;
        #pragma unroll
        for (int y = 1; y < SW; y++) {
            acc += sp[((size_t)y * SW + (x + 1)) * DCH + d];
            gs[((size_t)y * SW + (x + 1)) * DD] = acc;
        }
    }
}

// ---------------------------------------------------------------------------
// Kernel 2: ROI mean via SAT lookup -> bf16 hi/lo split operand A.
// ---------------------------------------------------------------------------
__global__ void pool_lookup_kernel(const float* __restrict__ boxes,
                                   const int* __restrict__ imh,
                                   const int* __restrict__ imw) {
    int idx = blockIdx.x * 256 + threadIdx.x;
    int d = idx % DD;
    int bn = idx / DD;
    int b = bn / NN;

    const float* box = boxes + (size_t)bn * 4;
    float sizeW = (float)(*imw);
    float sizeH = (float)(*imh);

    int px1 = (int)floorf(floorf(box[0] * sizeW) / sizeW * (float)TH);
    int py1 = (int)floorf(floorf(box[1] * sizeH) / sizeH * (float)TH);
    int px2 = (int)floorf(floorf(box[2] * sizeW) / sizeW * (float)TH);
    int py2 = (int)floorf(floorf(box[3] * sizeH) / sizeH * (float)TH);
    px1 = min(max(px1, 0), TH - 1);
    py1 = min(max(py1, 0), TH - 1);
    px2 = min(max(px2, 1), TH);
    py2 = min(max(py2, 1), TH);
    if (px2 <= px1) px2 = px1 + 1;
    if (py2 <= py1) py2 = py1 + 1;

    float inv_cnt = 1.f / (float)((px2 - px1) * (py2 - py1));

    const float* S = g_sat + ((size_t)b * SW * SW) * DD + d;
    float s22 = S[((size_t)py2 * SW + px2) * DD];
    float s12 = S[((size_t)py1 * SW + px2) * DD];
    float s21 = S[((size_t)py2 * SW + px1) * DD];
    float s11 = S[((size_t)py1 * SW + px1) * DD];

    float p = (s22 - s12 - s21 + s11) * inv_cnt;
    __nv_bfloat16 hi = __float2bfloat16(p);
    __nv_bfloat16 lo = __float2bfloat16(p - __bfloat162float(hi));
    ((__nv_bfloat16*)g_pA_hi)[(size_t)bn * DD + d] = hi;
    ((__nv_bfloat16*)g_pA_lo)[(size_t)bn * DD + d] = lo;
}

// ---------------------------------------------------------------------------
// Kernel 3: transpose + bf16 hi/lo split of W1.
// ---------------------------------------------------------------------------
__global__ void convert_w_kernel(const float* __restrict__ W1) {
    __shared__ float tile[32][33];
    int s = blockIdx.z;
    int k0 = blockIdx.x * 32;
    int n0 = blockIdx.y * 32;
    int tx = threadIdx.x % 32, ty = threadIdx.x / 32;

    #pragma unroll
    for (int j = 0; j < 4; j++) {
        int k = k0 + ty + j * 8;
        tile[ty + j * 8][tx] = W1[((size_t)(s * DD + k)) * HH + n0 + tx];
    }
    __syncthreads();

    __nv_bfloat16* Whi = (__nv_bfloat16*)g_wt_hi;
    __nv_bfloat16* Wlo = (__nv_bfloat16*)g_wt_lo;
    #pragma unroll
    for (int j = 0; j < 4; j++) {
        int n = n0 + ty + j * 8;
        float v = tile[tx][ty + j * 8];
        __nv_bfloat16 hi = __float2bfloat16(v);
        __nv_bfloat16 lo = __float2bfloat16(v - __bfloat162float(hi));
        size_t o = ((size_t)(s * HH + n)) * DD + k0 + tx;
        Whi[o] = hi;
        Wlo[o] = lo;
    }
}

// ---------------------------------------------------------------------------
// Kernel 4: HMMA (mma.sync) bf16 split GEMM (round-6 version, passing).
// ---------------------------------------------------------------------------
#define KCH 32
#define NCHUNK (DD / KCH)     // 24
#define PITCHB 80
#define T_AHI 0
#define T_ALO 5120
#define T_BHI 10240
#define T_BLO 15360

__global__ void __launch_bounds__(128)
hmma_gemm_kernel(const float* __restrict__ b1) {
    __shared__ __align__(16) char smem[4 * 5120];
    uint32_t sb = smem_u32(smem);

    int tid = threadIdx.x;
    int wid = tid / 32, lid = tid % 32;
    int wy = wid / 2, wx = wid % 2;

    int nt = blockIdx.x;
    int m0 = blockIdx.y * 64;
    int nrow0 = nt * 64;

    const char* Ahi = (const char*)g_pA_hi;
    const char* Alo = (const char*)g_pA_lo;
    const char* Bhi = (const char*)g_wt_hi;
    const char* Blo = (const char*)g_wt_lo;

    float acc[2][4][4] = {};
    uint4 pa_hi[2], pa_lo[2], pb_hi[2], pb_lo[2];

    #pragma unroll
    for (int t = 0; t < 2; t++) {
        int idx = tid + t * 128;
        int r = idx >> 2, g = idx & 3;
        size_t oa = ((size_t)(m0 + r) * DD) * 2 + (size_t)g * 16;
        size_t ob = ((size_t)(nrow0 + r) * DD) * 2 + (size_t)g * 16;
        pa_hi[t] = *(const uint4*)(Ahi + oa);
        pa_lo[t] = *(const uint4*)(Alo + oa);
        pb_hi[t] = *(const uint4*)(Bhi + ob);
        pb_lo[t] = *(const uint4*)(Blo + ob);
    }

    int la_row = lid % 16, la_blk = lid / 16;
    int lb_row = lid % 8, lb_blk = (lid / 8) & 1;

    for (int ch = 0; ch < NCHUNK; ch++) {
        #pragma unroll
        for (int t = 0; t < 2; t++) {
            int idx = tid + t * 128;
            int r = idx >> 2, g = idx & 3;
            uint32_t off = (uint32_t)(r * PITCHB + g * 16);
            *(uint4*)(smem + T_AHI + off) = pa_hi[t];
            *(uint4*)(smem + T_ALO + off) = pa_lo[t];
            *(uint4*)(smem + T_BHI + off) = pb_hi[t];
            *(uint4*)(smem + T_BLO + off) = pb_lo[t];
        }
        __syncthreads();

        if (ch + 1 < NCHUNK) {
            int kb = (ch + 1) * KCH;
            #pragma unroll
            for (int t = 0; t < 2; t++) {
                int idx = tid + t * 128;
                int r = idx >> 2, g = idx & 3;
                size_t oa = ((size_t)(m0 + r) * DD + kb) * 2 + (size_t)g * 16;
                size_t ob = ((size_t)(nrow0 + r) * DD + kb) * 2 + (size_t)g * 16;
                pa_hi[t] = *(const uint4*)(Ahi + oa);
                pa_lo[t] = *(const uint4*)(Alo + oa);
                pb_hi[t] = *(const uint4*)(Bhi + ob);
                pb_lo[t] = *(const uint4*)(Blo + ob);
            }
        }

        #pragma unroll
        for (int ks = 0; ks < 2; ks++) {
            int kofs = ks * 16;
            uint32_t ahi[2][4], alo[2][4], bhi[4][2], blo[4][2];

            #pragma unroll
            for (int mf = 0; mf < 2; mf++) {
                uint32_t ad = sb + (uint32_t)((wy * 32 + mf * 16 + la_row) * PITCHB
                                              + (kofs + la_blk * 8) * 2);
                ldm_x4(ahi[mf], T_AHI + ad);
                ldm_x4(alo[mf], T_ALO + ad);
            }
            #pragma unroll
            for (int nf = 0; nf < 4; nf++) {
                uint32_t bd = sb + (uint32_t)((wx * 32 + nf * 8 + lb_row) * PITCHB
                                              + (kofs + lb_blk * 8) * 2);
                ldm_x2(bhi[nf], T_BHI + bd);
                ldm_x2(blo[nf], T_BLO + bd);
            }

            #pragma unroll
            for (int mf = 0; mf < 2; mf++) {
                #pragma unroll
                for (int nf = 0; nf < 4; nf++) {
                    mma16816(acc[mf][nf], ahi[mf], bhi[nf]);
                    mma16816(acc[mf][nf], alo[mf], bhi[nf]);
                    mma16816(acc[mf][nf], ahi[mf], blo[nf]);
                }
            }
        }
        __syncthreads();
    }

    bool is_ha = (nt < 12);
    float* C = is_ha ? g_ha : g_hb;
    int n0 = (is_ha ? nt : nt - 12) * 64;

    #pragma unroll
    for (int mf = 0; mf < 2; mf++) {
        #pragma unroll
        for (int nf = 0; nf < 4; nf++) {
            int m = m0 + wy * 32 + mf * 16 + lid / 4;
            int n = n0 + wx * 32 + nf * 8 + 2 * (lid % 4);
            float2 bia = make_float2(0.f, 0.f);
            if (is_ha) bia = *(const float2*)(b1 + n);
            if (m < BN) {
                float2 v = make_float2(acc[mf][nf][0] + bia.x,
                                       acc[mf][nf][1] + bia.y);
                *(float2*)(C + (size_t)m * HH + n) = v;
            }
            if (m + 8 < BN) {
                float2 v = make_float2(acc[mf][nf][2] + bia.x,
                                       acc[mf][nf][3] + bia.y);
                *(float2*)(C + (size_t)(m + 8) * HH + n) = v;
            }
        }
    }
}

// ---------------------------------------------------------------------------
// Kernel 5: pairwise relu-dot + sigmoid, packed f32x2 math.
// ---------------------------------------------------------------------------
#define KC 64
__global__ void pair_kernel(const float* __restrict__ W2,
                            const float* __restrict__ b2,
                            float* __restrict__ out) {
    int b = blockIdx.z;
    int i0 = blockIdx.y * 32;
    int j0 = blockIdx.x * 32;

    __shared__ float has[32][KC + 4];
    __shared__ float hbs[32][KC + 4];
    __shared__ float w2s[KC];

    int tid = threadIdx.x;
    int tx = tid % 16, ty = tid / 16;

    ull acc[2][2];   // packed partial sums (even-k, odd-k)
    acc[0][0] = acc[0][1] = acc[1][0] = acc[1][1] = pack2(0.f, 0.f);

    for (int k0 = 0; k0 < HH; k0 += KC) {
        #pragma unroll
        for (int t = 0; t < 2; t++) {
            int idx = tid + t * 256;
            int r = idx / 16, c4 = idx % 16;
            int i = i0 + r;
            float4 va = make_float4(0.f, 0.f, 0.f, 0.f);
            if (i < NN) va = *(const float4*)&g_ha[((size_t)b * NN + i) * HH + k0 + c4 * 4];
            *(float4*)&has[r][c4 * 4] = va;
            int j = j0 + r;
            float4 vb = make_float4(0.f, 0.f, 0.f, 0.f);
            if (j < NN) vb = *(const float4*)&g_hb[((size_t)b * NN + j) * HH + k0 + c4 * 4];
            *(float4*)&hbs[r][c4 * 4] = vb;
        }
        if (tid < KC / 4)
            *(float4*)&w2s[tid * 4] = *(const float4*)&W2[k0 + tid * 4];
        __syncthreads();

        #pragma unroll
        for (int kk = 0; kk < KC; kk += 4) {
            float4 a0 = *(const float4*)&has[ty * 2][kk];
            float4 a1 = *(const float4*)&has[ty * 2 + 1][kk];
            float4 c0 = *(const float4*)&hbs[tx * 2][kk];
            float4 c1 = *(const float4*)&hbs[tx * 2 + 1][kk];
            float4 w  = *(const float4*)&w2s[kk];

            ull a0p0 = pack2(a0.x, a0.y), a0p1 = pack2(a0.z, a0.w);
            ull a1p0 = pack2(a1.x, a1.y), a1p1 = pack2(a1.z, a1.w);
            ull c0p0 = pack2(c0.x, c0.y), c0p1 = pack2(c0.z, c0.w);
            ull c1p0 = pack2(c1.x, c1.y), c1p1 = pack2(c1.z, c1.w);
            ull wp0  = pack2(w.x, w.y),   wp1  = pack2(w.z, w.w);

            fma2(acc[0][0], relu2(add2(a0p0, c0p0)), wp0);
            fma2(acc[0][0], relu2(add2(a0p1, c0p1)), wp1);
            fma2(acc[0][1], relu2(add2(a0p0, c1p0)), wp0);
            fma2(acc[0][1], relu2(add2(a0p1, c1p1)), wp1);
            fma2(acc[1][0], relu2(add2(a1p0, c0p0)), wp0);
            fma2(acc[1][0], relu2(add2(a1p1, c0p1)), wp1);
            fma2(acc[1][1], relu2(add2(a1p0, c1p0)), wp0);
            fma2(acc[1][1], relu2(add2(a1p1, c1p1)), wp1);
        }
        __syncthreads();
    }

    float bb = b2[0];
    #pragma unroll
    for (int ii = 0; ii < 2; ii++) {
        #pragma unroll
        for (int jj = 0; jj < 2; jj++) {
            int i = i0 + ty * 2 + ii;
            int j = j0 + tx * 2 + jj;
            if (i < NN && j < NN) {
                float lo, hi;
                unpack2(acc[ii][jj], lo, hi);
                float x = lo + hi + bb;
                out[(size_t)b * NN * NN + (size_t)i * NN + j] =
                    1.f / (1.f + expf(-x));
            }
        }
    }
}

// ---------------------------------------------------------------------------
// Launch.  inputs: patch_tokens, boxes, W1, b1, W2, b2, img_h, img_w
// ---------------------------------------------------------------------------
extern "C" void kernel_launch(void* const* d_in, const int* in_sizes, int n_in,
                              void* d_out, int out_size) {
    const float* pt    = (const float*)d_in[0];
    const float* boxes = (const float*)d_in[1];
    const float* W1    = (const float*)d_in[2];
    const float* b1    = (const float*)d_in[3];
    const float* W2    = (const float*)d_in[4];
    const float* b2    = (const float*)d_in[5];
    const int*   imh   = (const int*)d_in[6];
    const int*   imw   = (const int*)d_in[7];
    float* out = (float*)d_out;

    static int configured = 0;
    if (!configured) {
        cudaFuncSetAttribute(sat_fused_kernel,
                             cudaFuncAttributeMaxDynamicSharedMemorySize,
                             SW * SW * DCH * (int)sizeof(float));
        configured = 1;
    }

    dim3 gs(BB, DD / DCH);            // (8, 24)
    sat_fused_kernel<<<gs, 256, SW * SW * DCH * sizeof(float)>>>(pt);

    pool_lookup_kernel<<<(BN * DD) / 256, 256>>>(boxes, imh, imw);

    dim3 gw(DD / 32, HH / 32, 2);     // (24, 24, 2)
    convert_w_kernel<<<gw, 256>>>(W1);

    dim3 gg(2 * HH / 64, (BN + 63) / 64);   // (24, 13)
    hmma_gemm_kernel<<<gg, 128>>>(b1);

    dim3 gp((NN + 31) / 32, (NN + 31) / 32, BB);
    pair_kernel<<<gp, 256>>>(W2, b2, out);
}